// round 14
// baseline (speedup 1.0000x reference)
#include <cuda_runtime.h>

#define NN 8
#define LL 6400
#define KK 100
#define CC 256
#define L2DIM (2*LL)
#define NCHUNK 25          // mask chunks of 256 l per n
#define NWORDS (NCHUNK*8)  // 200 ballot words per n
#define RCH 64             // reduce chunks per n (200 rows each)

// Scratch (no allocations allowed) — fully rewritten every launch.
__device__ float    d_partT[NN][KK][RCH]; // transposed partials
__device__ unsigned d_bits[NN][NWORDS];   // selection bitmask, 32 l per word
__device__ int      d_srcrow[NN][LL];     // inverse perm: dst rank -> src row
__device__ int      d_len[NN];
__device__ int      d_rctr[NN];           // reduce ticket; reset in-kernel
__device__ int      d_mctr[NN];           // mask ticket;   reset in-kernel

// ============ reduce + tail-fused mask (argmax/ballot/scan/perm) ============
// grid (RCH, NN) = 512 blocks, block 256 (250 active in phase 1).
// Phase 1: chunk = 200 rows = 5000 float4 streamed fully contiguously
// (4*250 = 1000 ≡ 0 mod 100 -> thread t's column phase 4*(t%25) is invariant).
// Phase 2: the LAST 25 ticket-holders per n become mask blocks; they wait only
// for straggler peers, then do argmax + ballot; the last mask block does the
// word scan, inverse permutation, d_len, out_mask, and resets tickets.
__global__ void __launch_bounds__(256)
tf_reduce_mask_kernel(const float* __restrict__ prob,
                      const float* __restrict__ topics,
                      float* __restrict__ out_mask) {
    int n = blockIdx.y;
    int x = blockIdx.x;
    int t = threadIdx.x;

    __shared__ float4 sred[250];
    __shared__ float  bv[128];
    __shared__ int    bi[128];
    __shared__ int    ps[256];
    __shared__ int    s_ind, s_tick, s_mtick;

    // ---------------- Phase 1: reduce chunk x ----------------
    {
        const float4* base =
            (const float4*)(prob + ((size_t)n * L2DIM + (size_t)x * 200) * KK);
        float4 acc = make_float4(0.f, 0.f, 0.f, 0.f);
        if (t < 250) {
            #pragma unroll
            for (int it = 0; it < 20; it++) {
                float4 v = __ldg(base + t + it * 250);
                acc.x += v.x; acc.y += v.y; acc.z += v.z; acc.w += v.w;
            }
            sred[t] = acc;
        }
        __syncthreads();
        if (t < 25) {
            float4 a = sred[t];
            #pragma unroll
            for (int g = 1; g < 10; g++) {
                float4 v = sred[t + 25 * g];
                a.x += v.x; a.y += v.y; a.z += v.z; a.w += v.w;
            }
            int k = 4 * t;
            d_partT[n][k    ][x] = a.x;
            d_partT[n][k + 1][x] = a.y;
            d_partT[n][k + 2][x] = a.z;
            d_partT[n][k + 3][x] = a.w;
        }
        __syncthreads();
        __threadfence();                       // release partT
        if (t == 0) s_tick = atomicAdd(&d_rctr[n], 1);
        __syncthreads();
    }

    int tick = s_tick;
    if (tick < RCH - NCHUNK) return;           // first 39 finishers exit
    int chunk = tick - (RCH - NCHUNK);         // 0..24: this block's mask chunk

    // ---------------- Phase 2: mask blocks (last 25 finishers) ----------------
    if (t == 0) {                              // wait for straggler peers only
        while (atomicAdd(&d_rctr[n], 0) < RCH) __nanosleep(32);
    }
    __syncthreads();
    __threadfence();                           // acquire partT

    // argmax_k S0[k]*S1[k]; top_k tie-break = lowest index first.
    if (t < 128) {
        float best = -1.0f; int bidx = KK;
        if (t < KK) {
            const float4* p = (const float4*)&d_partT[n][t][0];   // 64 floats
            float s0 = 0.f, s1 = 0.f;
            #pragma unroll
            for (int c = 0; c < 8; c++) {          // chunks 0..31 = half 0
                float4 v = __ldcg(p + c);
                s0 += (v.x + v.y) + (v.z + v.w);
            }
            #pragma unroll
            for (int c = 8; c < 16; c++) {         // chunks 32..63 = half 1
                float4 v = __ldcg(p + c);
                s1 += (v.x + v.y) + (v.z + v.w);
            }
            best = s0 * s1; bidx = t;
        }
        bv[t] = best; bi[t] = bidx;
    }
    __syncthreads();
    for (int s = 64; s > 0; s >>= 1) {
        if (t < s) {
            if (bv[t+s] > bv[t] || (bv[t+s] == bv[t] && bi[t+s] < bi[t])) {
                bv[t] = bv[t+s]; bi[t] = bi[t+s];
            }
        }
        __syncthreads();
    }
    if (t == 0) s_ind = bi[0];
    __syncthreads();

    int l = chunk * 256 + t;
    float v = __ldg(topics + ((size_t)n * L2DIM + l) * KK + s_ind);
    unsigned ballot = __ballot_sync(0xFFFFFFFFu, v > 0.5f);
    if ((t & 31) == 0) d_bits[n][chunk * 8 + (t >> 5)] = ballot;

    __threadfence();                           // release d_bits
    if (t == 0) s_mtick = atomicAdd(&d_mctr[n], 1);
    __syncthreads();
    if (s_mtick != NCHUNK - 1) return;
    __threadfence();                           // acquire all d_bits

    // ---------------- elected block: scan + inverse perm + out_mask ----------
    unsigned word = (t < NWORDS) ? __ldcg(&d_bits[n][t]) : 0u;
    int p = __popc(word);
    ps[t] = p;
    __syncthreads();
    for (int off = 1; off < 256; off <<= 1) {
        int xv = (t >= off) ? ps[t - off] : 0;
        __syncthreads();
        ps[t] += xv;
        __syncthreads();
    }
    int tot = ps[NWORDS - 1];
    if (t == 0) {
        d_len[n] = tot;
        d_rctr[n] = 0;                         // safe: all waiters passed
        d_mctr[n] = 0;                         // reset for graph replay
    }
    if (t < NWORDS) {                          // inverse permutation
        int off = ps[t] - p;
        unsigned w = word;
        int base = t * 32;
        while (w) {
            int b = __ffs(w) - 1;
            d_srcrow[n][off++] = base + b;
            w &= w - 1;
        }
    }
    float* m = out_mask + (size_t)n * LL;
    #pragma unroll
    for (int i = t; i < LL; i += 256) m[i] = (i < tot) ? 1.0f : 0.0f;
}

// -------------------------------------------- gather compact + zero-fill
// grid (LL/16, NN), block (64,4). Each thread handles 4 independent dst rows
// (ty + 4j) -> 4 in-flight loads, perfectly sequential streaming writes.
__global__ void tf_gather_kernel(const float* __restrict__ feat,
                                 float* __restrict__ out) {
    int n = blockIdx.y;
    int t = threadIdx.x;            // 64 lanes = one 1KB row
    int l0 = blockIdx.x * 16 + threadIdx.y;
    int len = d_len[n];

    int  l[4]; bool v[4]; int s[4]; float4 val[4];
    #pragma unroll
    for (int j = 0; j < 4; j++) {
        l[j] = l0 + 4*j;
        v[j] = l[j] < len;
        s[j] = v[j] ? d_srcrow[n][l[j]] : 0;   // L2-resident broadcast
        val[j] = make_float4(0.f, 0.f, 0.f, 0.f);
    }
    #pragma unroll
    for (int j = 0; j < 4; j++)
        if (v[j]) val[j] = ((const float4*)(feat + ((size_t)n*LL + s[j]) * CC))[t];
    #pragma unroll
    for (int j = 0; j < 4; j++)
        ((float4*)(out + ((size_t)n*LL + l[j]) * CC))[t] = val[j];
}

extern "C" void kernel_launch(void* const* d_in, const int* in_sizes, int n_in,
                              void* d_out, int out_size) {
    const float* feat   = (const float*)d_in[0];   // (8, 6400, 256)
    const float* prob   = (const float*)d_in[1];   // (8, 12800, 100)
    const float* topics = (const float*)d_in[2];   // (8, 12800, 100)
    // d_in[3] = n_samples: only top-1 index is consumed -> argmax; unused here.

    float* out_feat = (float*)d_out;               // (8, 6400, 256)
    float* out_mask = out_feat + (size_t)NN*LL*CC; // (8, 6400)

    tf_reduce_mask_kernel<<<dim3(RCH, NN), 256>>>(prob, topics, out_mask);
    tf_gather_kernel<<<dim3(LL/16, NN), dim3(64, 4)>>>(feat, out_feat);
}

// round 15
// speedup vs baseline: 1.1925x; 1.1925x over previous
#include <cuda_runtime.h>

#define NN 8
#define LL 6400
#define KK 100
#define CC 256
#define L2DIM (2*LL)
#define NCHUNK 25          // mask chunks of 256 l per n
#define NWORDS (NCHUNK*8)  // 200 ballot words per n
#define RCH 64             // reduce chunks per n (200 rows each)

#define GDC_LAUNCH() asm volatile("griddepcontrol.launch_dependents;" ::: "memory")
#define GDC_WAIT()   asm volatile("griddepcontrol.wait;" ::: "memory")

// Scratch (no allocations allowed) — fully rewritten every launch.
__device__ float    d_partT[NN][KK][RCH]; // transposed partials
__device__ unsigned d_bits[NN][NWORDS];   // selection bitmask, 32 l per word
__device__ int      d_srcrow[NN][LL];     // inverse perm: dst rank -> src row
__device__ int      d_len[NN];
__device__ int      d_ticket[NN];         // last-block election; reset each launch

// -------------------------------------------- column partial sums, float4 stream
// grid (RCH, NN), block 256 (250 active). Chunk = 200 rows = 5000 float4
// streamed fully contiguously (4*250 = 1000 ≡ 0 mod 100 -> column phase
// 4*(t%25) loop-invariant, rows advance 10/iter).
__global__ void tf_reduce_kernel(const float* __restrict__ prob) {
    int n = blockIdx.y;
    int chunk = blockIdx.x;
    int t = threadIdx.x;
    const float4* base = (const float4*)(prob + ((size_t)n * L2DIM + (size_t)chunk * 200) * KK);

    float4 acc = make_float4(0.f, 0.f, 0.f, 0.f);
    if (t < 250) {
        #pragma unroll
        for (int it = 0; it < 20; it++) {
            float4 v = __ldg(base + t + it * 250);
            acc.x += v.x; acc.y += v.y; acc.z += v.z; acc.w += v.w;
        }
    }
    __shared__ float4 s[250];
    if (t < 250) s[t] = acc;
    __syncthreads();
    if (t < 25) {
        float4 a = s[t];
        #pragma unroll
        for (int g = 1; g < 10; g++) {
            float4 v = s[t + 25 * g];
            a.x += v.x; a.y += v.y; a.z += v.z; a.w += v.w;
        }
        int k = 4 * t;
        d_partT[n][k    ][chunk] = a.x;
        d_partT[n][k + 1][chunk] = a.y;
        d_partT[n][k + 2][chunk] = a.z;
        d_partT[n][k + 3][chunk] = a.w;
    }
    GDC_LAUNCH();                  // dependents may begin their preamble
}

// ---------------- fused argmax + ballot + (last block) scan/perm/mask --------
// grid (NCHUNK, NN), block 256. Redundant deterministic argmax per block
// (contiguous 256B read/thread); top_k tie-break = lowest index first.
// Last block per n (atomic ticket) does scan, inverse perm, d_len, out_mask.
__global__ void tf_maskargmax_kernel(const float* __restrict__ topics,
                                     float* __restrict__ out_mask) {
    int n = blockIdx.y;
    int t = threadIdx.x;
    __shared__ float bv[128];
    __shared__ int   bi[128];
    __shared__ int   s_ind;
    __shared__ int   s_last;

    GDC_WAIT();                    // partT now complete + visible

    if (t < 128) {
        float best = -1.0f; int bidx = KK;
        if (t < KK) {
            const float4* p = (const float4*)&d_partT[n][t][0];   // 64 floats
            float s0 = 0.f, s1 = 0.f;
            #pragma unroll
            for (int c = 0; c < 8; c++) {        // chunks 0..31 = half 0
                float4 v = __ldg(p + c);
                s0 += (v.x + v.y) + (v.z + v.w);
            }
            #pragma unroll
            for (int c = 8; c < 16; c++) {       // chunks 32..63 = half 1
                float4 v = __ldg(p + c);
                s1 += (v.x + v.y) + (v.z + v.w);
            }
            best = s0 * s1; bidx = t;
        }
        bv[t] = best; bi[t] = bidx;
    }
    __syncthreads();
    for (int s = 64; s > 0; s >>= 1) {
        if (t < s) {
            if (bv[t+s] > bv[t] || (bv[t+s] == bv[t] && bi[t+s] < bi[t])) {
                bv[t] = bv[t+s]; bi[t] = bi[t+s];
            }
        }
        __syncthreads();
    }
    if (t == 0) s_ind = bi[0];
    __syncthreads();

    int ind = s_ind;
    int l = blockIdx.x * 256 + t;
    float v = __ldg(topics + ((size_t)n * L2DIM + l) * KK + ind);
    unsigned ballot = __ballot_sync(0xFFFFFFFFu, v > 0.5f);
    if ((t & 31) == 0) d_bits[n][blockIdx.x * 8 + (t >> 5)] = ballot;

    // ---- last-block election (release: fence before ticket) ----
    __threadfence();
    if (t == 0) s_last = atomicAdd(&d_ticket[n], 1);
    __syncthreads();
    if (s_last != NCHUNK - 1) { GDC_LAUNCH(); return; }
    __threadfence();               // acquire: all blocks' d_bits now visible

    // word-popcount exclusive scan over 200 words
    __shared__ int ps[256];
    unsigned word = (t < NWORDS) ? d_bits[n][t] : 0u;
    int p = __popc(word);
    ps[t] = p;
    __syncthreads();
    for (int off = 1; off < 256; off <<= 1) {
        int x = (t >= off) ? ps[t - off] : 0;
        __syncthreads();
        ps[t] += x;
        __syncthreads();
    }
    int tot = ps[NWORDS - 1];
    if (t == 0) { d_len[n] = tot; d_ticket[n] = 0; }   // reset for graph replay

    // inverse permutation: emit src row index for each set bit
    if (t < NWORDS) {
        int off = ps[t] - p;
        unsigned w = word;
        int base = t * 32;
        while (w) {
            int b = __ffs(w) - 1;
            d_srcrow[n][off++] = base + b;
            w &= w - 1;
        }
    }

    float* m = out_mask + (size_t)n * LL;
    #pragma unroll
    for (int i = t; i < LL; i += 256) m[i] = (i < tot) ? 1.0f : 0.0f;
    GDC_LAUNCH();
}

// -------------------------------------------- gather compact + zero-fill
// grid (LL/8, NN), block (64,4). Each thread handles 2 independent dst rows
// (ty and ty+4) -> 2 in-flight loads, perfectly sequential streaming writes.
__global__ void tf_gather_kernel(const float* __restrict__ feat,
                                 float* __restrict__ out) {
    int n = blockIdx.y;
    int t = threadIdx.x;            // 64 lanes = one 1KB row
    int l1 = blockIdx.x * 8 + threadIdx.y;
    int l2 = l1 + 4;
    const float* fsrc = feat + (size_t)n * LL * CC;
    float*       dst  = out  + (size_t)n * LL * CC;

    GDC_WAIT();                     // perm + len now complete + visible

    int len = d_len[n];
    bool v1 = l1 < len, v2 = l2 < len;
    int s1 = v1 ? d_srcrow[n][l1] : 0;     // L2-resident broadcast
    int s2 = v2 ? d_srcrow[n][l2] : 0;

    float4 a = make_float4(0.f, 0.f, 0.f, 0.f);
    float4 b = a;
    if (v1) a = ((const float4*)(fsrc + (size_t)s1 * CC))[t];
    if (v2) b = ((const float4*)(fsrc + (size_t)s2 * CC))[t];

    ((float4*)(dst + (size_t)l1 * CC))[t] = a;
    ((float4*)(dst + (size_t)l2 * CC))[t] = b;
}

extern "C" void kernel_launch(void* const* d_in, const int* in_sizes, int n_in,
                              void* d_out, int out_size) {
    const float* feat   = (const float*)d_in[0];   // (8, 6400, 256)
    const float* prob   = (const float*)d_in[1];   // (8, 12800, 100)
    const float* topics = (const float*)d_in[2];   // (8, 12800, 100)
    // d_in[3] = n_samples: only top-1 index is consumed -> argmax; unused here.

    float* out_feat = (float*)d_out;               // (8, 6400, 256)
    float* out_mask = out_feat + (size_t)NN*LL*CC; // (8, 6400)

    tf_reduce_kernel<<<dim3(RCH, NN), 256>>>(prob);

    cudaLaunchAttribute attr[1];
    attr[0].id = cudaLaunchAttributeProgrammaticStreamSerialization;
    attr[0].val.programmaticStreamSerializationAllowed = 1;

    {
        cudaLaunchConfig_t cfg = {};
        cfg.gridDim  = dim3(NCHUNK, NN);
        cfg.blockDim = dim3(256);
        cfg.stream   = 0;
        cfg.attrs    = attr;
        cfg.numAttrs = 1;
        cudaLaunchKernelEx(&cfg, tf_maskargmax_kernel, topics, out_mask);
    }
    {
        cudaLaunchConfig_t cfg = {};
        cfg.gridDim  = dim3(LL/8, NN);
        cfg.blockDim = dim3(64, 4);
        cfg.stream   = 0;
        cfg.attrs    = attr;
        cfg.numAttrs = 1;
        cudaLaunchKernelEx(&cfg, tf_gather_kernel, feat, out_feat);
    }
}